// round 5
// baseline (speedup 1.0000x reference)
#include <cuda_runtime.h>

#define POOL 7
#define NROI 32
#define NB   8
#define NC   1024
#define IMG_W 64
#define IMG_H 64
#define PP   (POOL * POOL)
#define NPOS (NB * NROI * PP)   // 12544
#define GRID 592                // 148 SMs * 4 resident CTAs

struct Quad { float4 a, b, c, d; };

__device__ __forceinline__ float4 blerp(const Quad& q, float wx, float wy) {
    float4 o;
    float t0, b0;
    t0 = q.a.x + (q.b.x - q.a.x) * wx;
    b0 = q.c.x + (q.d.x - q.c.x) * wx;
    o.x = t0 + (b0 - t0) * wy;
    t0 = q.a.y + (q.b.y - q.a.y) * wx;
    b0 = q.c.y + (q.d.y - q.c.y) * wx;
    o.y = t0 + (b0 - t0) * wy;
    t0 = q.a.z + (q.b.z - q.a.z) * wx;
    b0 = q.c.z + (q.d.z - q.c.z) * wx;
    o.z = t0 + (b0 - t0) * wy;
    t0 = q.a.w + (q.b.w - q.a.w) * wx;
    b0 = q.c.w + (q.d.w - q.c.w) * wx;
    o.w = t0 + (b0 - t0) * wy;
    return o;
}

// Compute the 4 gather pointers + weights + output index for a flat position.
// pos is batch-major: pos = ((b*NROI + r)*PP + pp), pp = py*POOL + px.
__device__ __forceinline__ void position_setup(
    int pos, const int* __restrict__ rois, const float* __restrict__ img,
    const float4*& p00, const float4*& p01, const float4*& p10, const float4*& p11,
    float& wx, float& wy, size_t& oidx)
{
    int b   = pos / (NROI * PP);
    int rem = pos - b * (NROI * PP);
    int r   = rem / PP;
    int pp  = rem - r * PP;
    int py  = pp / POOL;
    int px  = pp - py * POOL;

    const int4 roi = __ldg((const int4*)rois + r);  // x, y, w, h

    float cx = ((float)px + 0.5f) * ((float)roi.z / (float)POOL) - 0.5f;
    float cy = ((float)py + 0.5f) * ((float)roi.w / (float)POOL) - 0.5f;
    float fx = floorf(cx);
    float fy = floorf(cy);
    int lox = max((int)fx, 0);
    int loy = max((int)fy, 0);
    int hix = min(max((int)ceilf(cx), 0), roi.z - 1);
    int hiy = min(max((int)ceilf(cy), 0), roi.w - 1);
    wx = cx - fx;
    wy = cy - fy;

    int X0 = roi.x + lox, X1 = roi.x + hix;
    int Y0 = roi.y + loy, Y1 = roi.y + hiy;

    const float* base = img + (size_t)b * (IMG_H * IMG_W * NC);
    p00 = (const float4*)(base + (size_t)(Y0 * IMG_W + X0) * NC);
    p01 = (const float4*)(base + (size_t)(Y0 * IMG_W + X1) * NC);
    p10 = (const float4*)(base + (size_t)(Y1 * IMG_W + X0) * NC);
    p11 = (const float4*)(base + (size_t)(Y1 * IMG_W + X1) * NC);

    // Output layout: (r, b, py, px, c) flattened
    oidx = ((((size_t)r * NB + b) * PP) + pp) * (NC / 4);
}

__global__ __launch_bounds__(256, 4)
void roi_persist_kernel(const float* __restrict__ img,
                        const int*   __restrict__ rois,
                        float*       __restrict__ out) {
    const int t = threadIdx.x;  // channel group of 4 floats (0..255)
    float4* o4 = (float4*)out;

    int pos = blockIdx.x;

    // Prologue: set up + issue loads for first position
    const float4 *p00, *p01, *p10, *p11;
    float wx_c, wy_c;
    size_t oidx_c;
    position_setup(pos, rois, img, p00, p01, p10, p11, wx_c, wy_c, oidx_c);
    Quad cur;
    cur.a = __ldg(p00 + t);
    cur.b = __ldg(p01 + t);
    cur.c = __ldg(p10 + t);
    cur.d = __ldg(p11 + t);

    while (pos < NPOS) {
        int npos = pos + GRID;
        Quad nxt;
        float wx_n = 0.f, wy_n = 0.f;
        size_t oidx_n = 0;
        if (npos < NPOS) {
            const float4 *q00, *q01, *q10, *q11;
            position_setup(npos, rois, img, q00, q01, q10, q11, wx_n, wy_n, oidx_n);
            nxt.a = __ldg(q00 + t);
            nxt.b = __ldg(q01 + t);
            nxt.c = __ldg(q10 + t);
            nxt.d = __ldg(q11 + t);
        }
        float4 o = blerp(cur, wx_c, wy_c);
        __stcs(o4 + oidx_c + t, o);

        cur = nxt;
        wx_c = wx_n;
        wy_c = wy_n;
        oidx_c = oidx_n;
        pos = npos;
    }
}

extern "C" void kernel_launch(void* const* d_in, const int* in_sizes, int n_in,
                              void* d_out, int out_size) {
    const float* img  = (const float*)d_in[0];
    const int*   rois = (const int*)d_in[1];
    if (n_in >= 2 && in_sizes[0] == NROI * 4) {
        img  = (const float*)d_in[1];
        rois = (const int*)d_in[0];
    }
    float* out = (float*)d_out;

    roi_persist_kernel<<<GRID, 256>>>(img, rois, out);
}